// round 9
// baseline (speedup 1.0000x reference)
#include <cuda_runtime.h>
#include <cstdint>

// Problem constants (fixed by the reference: N=64, T=2048, F=256)
#define CBS_N 64
#define CBS_T 2048
#define CBS_F 256
#define CBS_F4 (CBS_F / 4)     // 64 float4 per (n, t) row
#define THREADS_PER_ROW 16      // each thread: 4 float4, INTERLEAVED stride 16
#define BLOCK_THREADS 512
#define ROWS_PER_BLOCK (BLOCK_THREADS / THREADS_PER_ROW)   // 32

// History:
//  - R4: 1 f4/thread, __stcs: bench 26.6 / kernel 25.9 (issue-bound 50%).
//  - R5: 4 consecutive f4/thread: 39.3 (uncoalesced, L1 73%).
//  - R6: 4 interleaved f4/thread, __stcs: kernel 24.6.
//  - R7: 8 interleaved f4/thread: kernel 25.5. MLP insensitive.
//  - R8: 4 interleaved, plain stores: kernel 24.45. Store policy insensitive.
//  => Kernel pinned ~24.5us = write-stream drain rate (DRAM traffic during
//     kernel ~103MB < 134MB writes: L2 absorbs the rest). At roofline.
//  - R9 (this): last knob: __ldcs streaming READS (x lines are read-once;
//    keep them from evicting dirty output lines in L2) + 512-thread blocks.

__device__ __forceinline__ int imax_(int a, int b) { return a > b ? a : b; }
__device__ __forceinline__ int imin_(int a, int b) { return a < b ? a : b; }

// grid = (T/32, N) = (64, 64), block = 512.
__global__ void __launch_bounds__(BLOCK_THREADS)
chunk_by_slices_v6_kernel(const float4* __restrict__ x,
                          const int* __restrict__ slices,
                          const int* __restrict__ lens,
                          float4* __restrict__ out,
                          float* __restrict__ out_lens) {
    const int n = blockIdx.y;

    // Per-row parameters; uniform across the block -> L1 broadcast.
    const int s = slices[2 * n];
    const int e = slices[2 * n + 1];
    const int chunk_len = imax_(e - s, 0);
    const int left_pad  = (chunk_len == 0) ? 0 : imax_(-s, 0);
    const int start_    = imax_(s, 0);
    const int end_      = imin_(e, lens[n]);
    const int slice_len = imax_(end_ - start_, 0);

    // Fused chunk_lens write: one thread per n.
    if (blockIdx.x == 0 && threadIdx.x == 0) {
        out_lens[n] = (float)chunk_len;
    }

    const int t  = blockIdx.x * ROWS_PER_BLOCK + (threadIdx.x >> 4);
    const int f0 = threadIdx.x & 15;   // interleaved: f0 + 16k, k = 0..3

    const bool valid = (t >= left_pad) && (t < left_pad + slice_len);

    int src = start_ + t - left_pad;
    src = imin_(imax_(src, 0), CBS_T - 1);

    float4 v0, v1, v2, v3;
    if (valid) {
        const float4* xr = &x[(n * CBS_T + src) * CBS_F4 + f0];
        v0 = __ldcs(xr + 0);    // read-once: evict-first in L2
        v1 = __ldcs(xr + 16);
        v2 = __ldcs(xr + 32);
        v3 = __ldcs(xr + 48);
    } else {
        v0 = v1 = v2 = v3 = make_float4(0.f, 0.f, 0.f, 0.f);
    }

    float4* op = &out[(n * CBS_T + t) * CBS_F4 + f0];
    op[0]  = v0;
    op[16] = v1;
    op[32] = v2;
    op[48] = v3;
}

extern "C" void kernel_launch(void* const* d_in, const int* in_sizes, int n_in,
                              void* d_out, int out_size) {
    const float4* x      = (const float4*)d_in[0];
    const int*    slices = (const int*)d_in[1];
    const int*    lens   = (const int*)d_in[2];
    float4*       out    = (float4*)d_out;

    const long long chunks_elems = (long long)CBS_N * CBS_T * CBS_F;
    float* out_lens = ((float*)d_out) + chunks_elems;

    dim3 block(BLOCK_THREADS);
    dim3 grid(CBS_T / ROWS_PER_BLOCK, CBS_N);  // (64, 64)
    chunk_by_slices_v6_kernel<<<grid, block>>>(x, slices, lens, out, out_lens);
}

// round 10
// speedup vs baseline: 1.1156x; 1.1156x over previous
#include <cuda_runtime.h>
#include <cstdint>

// Problem constants (fixed by the reference: N=64, T=2048, F=256)
#define CBS_N 64
#define CBS_T 2048
#define CBS_F 256
#define CBS_F4 (CBS_F / 4)     // 64 float4 per (n, t) row
#define THREADS_PER_ROW 16      // each thread: 4 float4, INTERLEAVED stride 16
#define ROWS_PER_BLOCK (256 / THREADS_PER_ROW)   // 16

// Final configuration (R10). Findings across R4-R9:
//  - slices/lens are int32 (JAX x64 off); chunk_lens written as float32.
//  - 4 interleaved float4/thread = fastest kernel (24.4-24.6us).
//  - Kernel time INVARIANT to MLP (4 vs 8), store policy (__stcs vs plain),
//    read policy (__ldcs vs default), block size (256 vs 512):
//    => at the mixed read/write HBM roofline (~170MB/iter @ ~7TB/s).
//  - Bench scatter 26.6-30.3us over identical kernels = environment drift.
//  - Tie-break by steady-state theory: default (cacheable) reads let the
//    ~35MB of valid x windows persist in the 126MB L2 across graph replays;
//    __stcs keeps the 134MB output stream from evicting them.

__device__ __forceinline__ int imax_(int a, int b) { return a > b ? a : b; }
__device__ __forceinline__ int imin_(int a, int b) { return a < b ? a : b; }

// grid = (T/16, N) = (128, 64), block = 256.
__global__ void chunk_by_slices_final_kernel(const float4* __restrict__ x,
                                             const int* __restrict__ slices,
                                             const int* __restrict__ lens,
                                             float4* __restrict__ out,
                                             float* __restrict__ out_lens) {
    const int n = blockIdx.y;

    // Per-row parameters; uniform across the block -> L1 broadcast.
    const int s = slices[2 * n];
    const int e = slices[2 * n + 1];
    const int chunk_len = imax_(e - s, 0);
    const int left_pad  = (chunk_len == 0) ? 0 : imax_(-s, 0);
    const int start_    = imax_(s, 0);
    const int end_      = imin_(e, lens[n]);
    const int slice_len = imax_(end_ - start_, 0);

    // Fused chunk_lens write: one thread per n.
    if (blockIdx.x == 0 && threadIdx.x == 0) {
        out_lens[n] = (float)chunk_len;
    }

    const int t  = blockIdx.x * ROWS_PER_BLOCK + (threadIdx.x >> 4);
    const int f0 = threadIdx.x & 15;   // interleaved: f0 + 16k, k = 0..3

    const bool valid = (t >= left_pad) && (t < left_pad + slice_len);

    int src = start_ + t - left_pad;
    src = imin_(imax_(src, 0), CBS_T - 1);

    float4 v0, v1, v2, v3;
    if (valid) {
        const float4* xr = &x[(n * CBS_T + src) * CBS_F4 + f0];
        v0 = __ldg(xr + 0);     // cacheable: valid windows stay L2-resident
        v1 = __ldg(xr + 16);    // across graph replays
        v2 = __ldg(xr + 32);
        v3 = __ldg(xr + 48);
    } else {
        v0 = v1 = v2 = v3 = make_float4(0.f, 0.f, 0.f, 0.f);
    }

    float4* op = &out[(n * CBS_T + t) * CBS_F4 + f0];
    __stcs(op + 0,  v0);        // output never re-read: evict-first
    __stcs(op + 16, v1);
    __stcs(op + 32, v2);
    __stcs(op + 48, v3);
}

extern "C" void kernel_launch(void* const* d_in, const int* in_sizes, int n_in,
                              void* d_out, int out_size) {
    const float4* x      = (const float4*)d_in[0];
    const int*    slices = (const int*)d_in[1];
    const int*    lens   = (const int*)d_in[2];
    float4*       out    = (float4*)d_out;

    const long long chunks_elems = (long long)CBS_N * CBS_T * CBS_F;
    float* out_lens = ((float*)d_out) + chunks_elems;

    dim3 block(256);
    dim3 grid(CBS_T / ROWS_PER_BLOCK, CBS_N);  // (128, 64)
    chunk_by_slices_final_kernel<<<grid, block>>>(x, slices, lens, out, out_lens);
}